// round 1
// baseline (speedup 1.0000x reference)
#include <cuda_runtime.h>

// Zero the scalar output (d_out is poisoned to 0xAA by the harness).
__global__ void pl_zero_kernel(float* out) {
    if (threadIdx.x == 0) out[0] = 0.0f;
}

// One warp per note. Lanes cooperatively (coalesced) load the note's frame
// segment from both f0 tracks, warp-reduce the sums, lane 0 computes the
// per-note mean difference and atomically accumulates 1/N into the loss if
// |diff| > 0.5.
//
// Determinism note: every atomic contribution is exactly 1/1024 (a dyadic
// rational), and all partial sums m/1024 with m <= 1024 are exactly
// representable in fp32, so the accumulation is order-independent.
__global__ void pitch_loss_kernel(const float* __restrict__ gen_f0,
                                  const float* __restrict__ t_f0,
                                  const int*   __restrict__ onset,
                                  const int*   __restrict__ offset,
                                  float*       __restrict__ out,
                                  int N) {
    int gwarp = (blockIdx.x * blockDim.x + threadIdx.x) >> 5;
    int lane  = threadIdx.x & 31;
    if (gwarp >= N) return;

    int a = onset[gwarp];
    int b = offset[gwarp];

    float sg = 0.0f, st = 0.0f;
    for (int i = a + lane; i < b; i += 32) {
        sg += gen_f0[i];
        st += t_f0[i];
    }

    #pragma unroll
    for (int o = 16; o > 0; o >>= 1) {
        sg += __shfl_down_sync(0xFFFFFFFFu, sg, o);
        st += __shfl_down_sync(0xFFFFFFFFu, st, o);
    }

    if (lane == 0) {
        float cnt  = (float)(b - a);
        float diff = fabsf(sg / cnt - st / cnt);
        if (diff > 0.5f) {
            atomicAdd(out, 1.0f / (float)N);
        }
    }
}

extern "C" void kernel_launch(void* const* d_in, const int* in_sizes, int n_in,
                              void* d_out, int out_size) {
    const float* gen_f0 = (const float*)d_in[0];
    const float* t_f0   = (const float*)d_in[1];
    const int*   onset  = (const int*)d_in[2];
    const int*   offset = (const int*)d_in[3];
    float* out = (float*)d_out;

    int N = in_sizes[2];  // number of notes

    pl_zero_kernel<<<1, 32>>>(out);

    const int THREADS = 256;                 // 8 warps per block
    int warps_needed = N;
    int blocks = (warps_needed * 32 + THREADS - 1) / THREADS;
    pitch_loss_kernel<<<blocks, THREADS>>>(gen_f0, t_f0, onset, offset, out, N);
}